// round 10
// baseline (speedup 1.0000x reference)
#include <cuda_runtime.h>
#include <cuda_fp16.h>
#include <cstdint>

// ============================================================================
// Flash attention via mma.sync.m16n8k16 (fp16 in, fp32 accum), sm_103 base ISA.
// B=4, L=4096, D=64.  S = Q K^T in 3xFP16 (compensated), online softmax (base-2
// domain, Q prescaled by log2e), O = P V fp16.
// R8: 8 warps/CTA, N-split (warp pair shares 16 q-rows, splits 64 keys 32/32).
//     Cross-warp softmax exchange via smem + named pair barriers (bar.sync id,64).
//     regs <= 128 -> 2 CTAs/SM -> 16 warps/SM (4/SMSP) for MUFU/HMMA overlap.
// ============================================================================

#define LSEQ 4096
#define BATCH 4
#define HD 64
#define BM 64
#define BN 64
#define NTILES (LSEQ / BN)     // 64
#define NTHREADS 256
#define QSTR 72
#define KSTR 72

#define TILE_HALFS (BN * KSTR)            // 4608
#define STAGE_HALFS (3 * TILE_HALFS)      // 13824
#define KH_OFF 0
#define KR_OFF TILE_HALFS
#define VH_OFF (2 * TILE_HALFS)
#define NSTAGES 3
#define PMX_B (NSTAGES * STAGE_HALFS * 2) // 82944: float[2][64] partial max
#define PLS_B (PMX_B + 512)               // float[2][64] partial sums
#define SMEM_BYTES (PLS_B + 512)          // 83968 B -> 2 CTAs/SM
#define QH_S 0
#define QR_S (BM * QSTR)
#define OSTR 68                            // epilogue O-merge row stride (floats)

__device__ __align__(16) __half g_qh[BATCH * LSEQ * HD];
__device__ __align__(16) __half g_qr[BATCH * LSEQ * HD];
__device__ __align__(16) __half g_kh[BATCH * LSEQ * HD];
__device__ __align__(16) __half g_kr[BATCH * LSEQ * HD];
__device__ __align__(16) __half g_vh[BATCH * LSEQ * HD];

// ---------------------------------------------------------------------------
__device__ __forceinline__ uint32_t smem_u32(const void* p) {
    uint32_t a;
    asm("{ .reg .u64 t; cvta.to.shared.u64 t, %1; cvt.u32.u64 %0, t; }" : "=r"(a) : "l"(p));
    return a;
}
__device__ __forceinline__ void cp16(uint32_t dst, const void* src) {
    asm volatile("cp.async.ca.shared.global [%0], [%1], 16;" :: "r"(dst), "l"(src));
}
#define CP_COMMIT() asm volatile("cp.async.commit_group;" ::: "memory")
#define CP_WAIT(n)  asm volatile("cp.async.wait_group %0;" :: "n"(n) : "memory")
#define PAIR_BAR(id) asm volatile("bar.sync %0, 64;" :: "r"(id) : "memory")

__device__ __forceinline__ void ldsm4(uint32_t addr, uint32_t& r0, uint32_t& r1,
                                      uint32_t& r2, uint32_t& r3) {
    asm volatile("ldmatrix.sync.aligned.m8n8.x4.shared.b16 {%0,%1,%2,%3}, [%4];"
                 : "=r"(r0), "=r"(r1), "=r"(r2), "=r"(r3) : "r"(addr));
}
__device__ __forceinline__ void ldsm4t(uint32_t addr, uint32_t& r0, uint32_t& r1,
                                       uint32_t& r2, uint32_t& r3) {
    asm volatile("ldmatrix.sync.aligned.m8n8.x4.trans.shared.b16 {%0,%1,%2,%3}, [%4];"
                 : "=r"(r0), "=r"(r1), "=r"(r2), "=r"(r3) : "r"(addr));
}
__device__ __forceinline__ void mma16816(float* c, const uint32_t* a, const uint32_t* b) {
    asm volatile("mma.sync.aligned.m16n8k16.row.col.f32.f16.f16.f32 "
                 "{%0,%1,%2,%3}, {%4,%5,%6,%7}, {%8,%9}, {%0,%1,%2,%3};"
                 : "+f"(c[0]), "+f"(c[1]), "+f"(c[2]), "+f"(c[3])
                 : "r"(a[0]), "r"(a[1]), "r"(a[2]), "r"(a[3]), "r"(b[0]), "r"(b[1]));
}
__device__ __forceinline__ uint32_t packh(__half a, __half b) {
    __half2 h = __halves2half2(a, b);
    return *(uint32_t*)&h;
}
__device__ __forceinline__ uint32_t pack2f(float a, float b) {
    __half2 h = __floats2half2_rn(a, b);
    return *(uint32_t*)&h;
}
__device__ __forceinline__ float ex2f(float x) {
    float y;
    asm("ex2.approx.f32 %0, %1;" : "=f"(y) : "f"(x));
    return y;
}

// ---------------------------------------------------------------------------
// prepass: Q scaled by log2(e) then split hi/resid; K split; V fp16.
// ---------------------------------------------------------------------------
__global__ void prep_kernel(const float4* __restrict__ Q, const float4* __restrict__ K,
                            const float4* __restrict__ V) {
    int i = blockIdx.x * blockDim.x + threadIdx.x;
    float4 q = Q[i], k = K[i], v = V[i];
    const float LG2E = 1.4426950408889634f;
    q.x *= LG2E; q.y *= LG2E; q.z *= LG2E; q.w *= LG2E;

    __half qhx = __float2half_rn(q.x), qhy = __float2half_rn(q.y),
           qhz = __float2half_rn(q.z), qhw = __float2half_rn(q.w);
    __half qrx = __float2half_rn(q.x - __half2float(qhx)),
           qry = __float2half_rn(q.y - __half2float(qhy)),
           qrz = __float2half_rn(q.z - __half2float(qhz)),
           qrw = __float2half_rn(q.w - __half2float(qhw));
    ((uint2*)g_qh)[i] = make_uint2(packh(qhx, qhy), packh(qhz, qhw));
    ((uint2*)g_qr)[i] = make_uint2(packh(qrx, qry), packh(qrz, qrw));

    __half khx = __float2half_rn(k.x), khy = __float2half_rn(k.y),
           khz = __float2half_rn(k.z), khw = __float2half_rn(k.w);
    __half krx = __float2half_rn(k.x - __half2float(khx)),
           kry = __float2half_rn(k.y - __half2float(khy)),
           krz = __float2half_rn(k.z - __half2float(khz)),
           krw = __float2half_rn(k.w - __half2float(khw));
    ((uint2*)g_kh)[i] = make_uint2(packh(khx, khy), packh(khz, khw));
    ((uint2*)g_kr)[i] = make_uint2(packh(krx, kry), packh(krz, krw));

    ((uint2*)g_vh)[i] = make_uint2(pack2f(v.x, v.y), pack2f(v.z, v.w));
}

// ---------------------------------------------------------------------------
__device__ __forceinline__ void issue_tile(uint32_t smb, int stage, int t, int tid,
                                           const __half* kh_g, const __half* kr_g,
                                           const __half* vh_g) {
    const int base = stage * STAGE_HALFS;
    const __half* ks = kh_g + (size_t)t * BN * HD;
    const __half* rs = kr_g + (size_t)t * BN * HD;
    const __half* vs = vh_g + (size_t)t * BN * HD;
#pragma unroll
    for (int i = 0; i < 2; i++) {
        int cid = tid + i * NTHREADS;          // 0..511
        int r = cid >> 3, c = cid & 7;
        uint32_t d = (uint32_t)(r * KSTR * 2 + c * 16);
        const size_t so = (size_t)r * HD + c * 8;
        cp16(smb + (uint32_t)(base + KH_OFF) * 2 + d, ks + so);
        cp16(smb + (uint32_t)(base + KR_OFF) * 2 + d, rs + so);
        cp16(smb + (uint32_t)(base + VH_OFF) * 2 + d, vs + so);
    }
}

__global__ __launch_bounds__(NTHREADS, 2)
void attn_mma(float* __restrict__ O) {
    extern __shared__ __half sh[];
    const uint32_t smb = smem_u32(sh);
    float* pmx = (float*)((char*)sh + PMX_B);   // [2][64]
    float* pls = (float*)((char*)sh + PLS_B);   // [2][64]
    const int tid = threadIdx.x, lane = tid & 31, wid = tid >> 5;
    const int g = lane >> 2, tg = lane & 3;
    const int rowgrp = wid & 3, half = wid >> 2;
    const int wr0 = rowgrp * 16;                // q-row base of this warp
    const int khalf = half * 32;                // key-half base within tile
    const int pairbar = rowgrp + 1;             // named barrier id (1..4)
    const int b = blockIdx.y, row0 = blockIdx.x * BM;

    const __half* qh_g = g_qh + (size_t)(b * LSEQ + row0) * HD;
    const __half* qr_g = g_qr + (size_t)(b * LSEQ + row0) * HD;
    const __half* kh_g = g_kh + (size_t)b * LSEQ * HD;
    const __half* kr_g = g_kr + (size_t)b * LSEQ * HD;
    const __half* vh_g = g_vh + (size_t)b * LSEQ * HD;
    float* Ob = O + (size_t)(b * LSEQ + row0) * HD;

    // ---- preamble: Q -> smem -> regs ----
#pragma unroll
    for (int i = 0; i < 2; i++) {
        int cid = tid + i * NTHREADS;          // 0..511
        int r = cid >> 3, c = cid & 7;
        const size_t so = (size_t)r * HD + c * 8;
        cp16(smb + (uint32_t)(QH_S + r * QSTR) * 2 + c * 16, qh_g + so);
        cp16(smb + (uint32_t)(QR_S + r * QSTR) * 2 + c * 16, qr_g + so);
    }
    CP_COMMIT();
    CP_WAIT(0);
    __syncthreads();

    uint32_t qh[4][4], qr[4][4];
    {
        const int arow = wr0 + (lane & 15);
        const int koff = (lane >> 4) << 3;
#pragma unroll
        for (int s = 0; s < 4; s++) {
            uint32_t a1 = smb + (uint32_t)(QH_S + arow * QSTR + 16 * s + koff) * 2;
            uint32_t a2 = smb + (uint32_t)(QR_S + arow * QSTR + 16 * s + koff) * 2;
            ldsm4(a1, qh[s][0], qh[s][1], qh[s][2], qh[s][3]);
            ldsm4(a2, qr[s][0], qr[s][1], qr[s][2], qr[s][3]);
        }
    }
    __syncthreads();   // Q area reusable by pipeline

    issue_tile(smb, 0, 0, tid, kh_g, kr_g, vh_g);
    CP_COMMIT();
    issue_tile(smb, 1, 1, tid, kh_g, kr_g, vh_g);
    CP_COMMIT();

    float o_[8][4];
#pragma unroll
    for (int j = 0; j < 8; j++)
#pragma unroll
        for (int q = 0; q < 4; q++) o_[j][q] = 0.f;
    float m0 = -1e30f, m1 = -1e30f, l0 = 0.f, l1 = 0.f;

    const int krow_off = (lane & 7) + ((lane >> 4) << 3);
    const int kcol_off = (lane & 8);
    const int vkey_off = (lane & 7) + (lane & 8);
    const int vcol_off = (lane >> 4) << 3;

    int stage = 0, stage2 = 2;

    for (int t = 0; t < NTILES; t++) {
        if (t + 2 < NTILES) { CP_WAIT(1); } else { CP_WAIT(0); }
        __syncthreads();
        if (t + 2 < NTILES) {
            issue_tile(smb, stage2, t + 2, tid, kh_g, kr_g, vh_g);
            CP_COMMIT();
        }

        const uint32_t kb = (uint32_t)(stage * STAGE_HALFS);

        // ---- S = Q K^T (3xFP16) over this warp's 32 keys ----
        float s_[4][4];
#pragma unroll
        for (int j = 0; j < 4; j++)
#pragma unroll
            for (int q = 0; q < 4; q++) s_[j][q] = 0.f;

#pragma unroll
        for (int s = 0; s < 4; s++) {
            uint32_t bb[4][2];
#pragma unroll
            for (int jj = 0; jj < 2; jj++) {
                uint32_t addr = smb + (kb + KH_OFF +
                    (uint32_t)((khalf + 16 * jj + krow_off) * KSTR + 16 * s + kcol_off)) * 2;
                ldsm4(addr, bb[2*jj][0], bb[2*jj][1], bb[2*jj+1][0], bb[2*jj+1][1]);
            }
#pragma unroll
            for (int j = 0; j < 4; j++) {
                mma16816(s_[j], qh[s], bb[j]);
                mma16816(s_[j], qr[s], bb[j]);
            }
#pragma unroll
            for (int jj = 0; jj < 2; jj++) {
                uint32_t addr = smb + (kb + KR_OFF +
                    (uint32_t)((khalf + 16 * jj + krow_off) * KSTR + 16 * s + kcol_off)) * 2;
                ldsm4(addr, bb[2*jj][0], bb[2*jj][1], bb[2*jj+1][0], bb[2*jj+1][1]);
            }
#pragma unroll
            for (int j = 0; j < 4; j++) mma16816(s_[j], qh[s], bb[j]);
        }

        // ---- partial max over this warp's 32 keys ----
        float m0t = s_[0][0], m1t = s_[0][2];
#pragma unroll
        for (int j = 0; j < 4; j++) {
            m0t = fmaxf(m0t, fmaxf(s_[j][0], s_[j][1]));
            m1t = fmaxf(m1t, fmaxf(s_[j][2], s_[j][3]));
        }
        m0t = fmaxf(m0t, __shfl_xor_sync(0xffffffffu, m0t, 1));
        m0t = fmaxf(m0t, __shfl_xor_sync(0xffffffffu, m0t, 2));
        m1t = fmaxf(m1t, __shfl_xor_sync(0xffffffffu, m1t, 1));
        m1t = fmaxf(m1t, __shfl_xor_sync(0xffffffffu, m1t, 2));

        // exchange max with partner warp (same rows, other key-half)
        if (tg == 0) {
            pmx[half * 64 + wr0 + g]     = m0t;
            pmx[half * 64 + wr0 + g + 8] = m1t;
        }
        PAIR_BAR(pairbar);
        m0t = fmaxf(m0t, pmx[(half ^ 1) * 64 + wr0 + g]);
        m1t = fmaxf(m1t, pmx[(half ^ 1) * 64 + wr0 + g + 8]);

        const float m0n = fmaxf(m0, m0t), m1n = fmaxf(m1, m1t);
        const float c0 = ex2f(m0 - m0n), c1 = ex2f(m1 - m1n);
        m0 = m0n; m1 = m1n;

        // ---- exp (base-2 domain) + partial row sums ----
        uint32_t pa[2][4];
        float r0s = 0.f, r1s = 0.f;
#pragma unroll
        for (int j = 0; j < 4; j++) {
            float e0 = ex2f(s_[j][0] - m0n);
            float e1 = ex2f(s_[j][1] - m0n);
            float e2 = ex2f(s_[j][2] - m1n);
            float e3 = ex2f(s_[j][3] - m1n);
            r0s += e0 + e1; r1s += e2 + e3;
            pa[j >> 1][(j & 1) ? 2 : 0] = pack2f(e0, e1);
            pa[j >> 1][(j & 1) ? 3 : 1] = pack2f(e2, e3);
        }
        r0s += __shfl_xor_sync(0xffffffffu, r0s, 1);
        r0s += __shfl_xor_sync(0xffffffffu, r0s, 2);
        r1s += __shfl_xor_sync(0xffffffffu, r1s, 1);
        r1s += __shfl_xor_sync(0xffffffffu, r1s, 2);

        // exchange partial sums with partner
        if (tg == 0) {
            pls[half * 64 + wr0 + g]     = r0s;
            pls[half * 64 + wr0 + g + 8] = r1s;
        }
        PAIR_BAR(pairbar);
        r0s += pls[(half ^ 1) * 64 + wr0 + g];
        r1s += pls[(half ^ 1) * 64 + wr0 + g + 8];

        l0 = l0 * c0 + r0s;
        l1 = l1 * c1 + r1s;
#pragma unroll
        for (int j = 0; j < 8; j++) {
            o_[j][0] *= c0; o_[j][1] *= c0;
            o_[j][2] *= c1; o_[j][3] *= c1;
        }

        // ---- O += P V over this warp's 32 keys ----
#pragma unroll
        for (int s = 0; s < 2; s++) {
            uint32_t vb[8][2];
#pragma unroll
            for (int jj = 0; jj < 4; jj++) {
                uint32_t addr = smb + (kb + VH_OFF +
                    (uint32_t)((khalf + 16 * s + vkey_off) * KSTR + 16 * jj + vcol_off)) * 2;
                ldsm4t(addr, vb[2*jj][0], vb[2*jj][1], vb[2*jj+1][0], vb[2*jj+1][1]);
            }
#pragma unroll
            for (int j = 0; j < 8; j++) mma16816(o_[j], pa[s], vb[j]);
        }

        stage = (stage == 2) ? 0 : stage + 1;
        stage2 = (stage2 == 2) ? 0 : stage2 + 1;
    }

    // ---- epilogue: merge partner partial O, normalize, store ----
    __syncthreads();                       // pipeline smem no longer needed
    float* obuf = (float*)sh;              // [64][OSTR]
    if (half == 1) {
#pragma unroll
        for (int j = 0; j < 8; j++) {
            *(float2*)&obuf[(wr0 + g) * OSTR + 8 * j + 2 * tg] =
                make_float2(o_[j][0], o_[j][1]);
            *(float2*)&obuf[(wr0 + g + 8) * OSTR + 8 * j + 2 * tg] =
                make_float2(o_[j][2], o_[j][3]);
        }
    }
    __syncthreads();
    if (half == 0) {
        const float inv0 = 1.0f / l0, inv1 = 1.0f / l1;
        const int r0g = wr0 + g, r1g = wr0 + g + 8;
#pragma unroll
        for (int j = 0; j < 8; j++) {
            float2 p0 = *(float2*)&obuf[r0g * OSTR + 8 * j + 2 * tg];
            float2 p1 = *(float2*)&obuf[r1g * OSTR + 8 * j + 2 * tg];
            float2 v0 = make_float2((o_[j][0] + p0.x) * inv0, (o_[j][1] + p0.y) * inv0);
            float2 v1 = make_float2((o_[j][2] + p1.x) * inv1, (o_[j][3] + p1.y) * inv1);
            *(float2*)&Ob[(size_t)r0g * HD + 8 * j + 2 * tg] = v0;
            *(float2*)&Ob[(size_t)r1g * HD + 8 * j + 2 * tg] = v1;
        }
    }
}

// ---------------------------------------------------------------------------
extern "C" void kernel_launch(void* const* d_in, const int* in_sizes, int n_in,
                              void* d_out, int out_size)
{
    const float* Q = (const float*)d_in[0];
    const float* K = (const float*)d_in[1];
    const float* V = (const float*)d_in[2];
    float*       O = (float*)d_out;

    const int n4 = BATCH * LSEQ * HD / 4;
    prep_kernel<<<n4 / 256, 256>>>((const float4*)Q, (const float4*)K, (const float4*)V);

    cudaFuncSetAttribute(attn_mma, cudaFuncAttributeMaxDynamicSharedMemorySize, SMEM_BYTES);
    dim3 grid(LSEQ / BM, BATCH);
    attn_mma<<<grid, NTHREADS, SMEM_BYTES>>>(O);
}

// round 11
// speedup vs baseline: 1.2702x; 1.2702x over previous
#include <cuda_runtime.h>
#include <cuda_fp16.h>
#include <cstdint>

// ============================================================================
// Flash attention via mma.sync.m16n8k16 (fp16 in, fp32 accum), sm_103 base ISA.
// B=4, L=4096, D=64.  S = Q K^T in 3xFP16 (compensated), online softmax in
// base-2 domain (Q prescaled by log2e), O = P V fp16.
// R10 = R7 (software-pipelined S, 4 warps, 2 CTAs/SM) minus softmax overhead:
//   - row sums via constant ones-column MMA (osum accumulator, rescaled online)
//   - ex2.approx base-2 exp (no FMUL), l recovered from osum at epilogue.
// ============================================================================

#define LSEQ 4096
#define BATCH 4
#define HD 64
#define BM 64
#define BN 64
#define NTILES (LSEQ / BN)     // 64
#define NTHREADS 128
#define QSTR 72
#define KSTR 72

#define TILE_HALFS (BN * KSTR)            // 4608
#define STAGE_HALFS (3 * TILE_HALFS)      // 13824
#define KH_OFF 0
#define KR_OFF TILE_HALFS
#define VH_OFF (2 * TILE_HALFS)
#define NSTAGES 3
#define SMEM_BYTES (NSTAGES * STAGE_HALFS * 2)   // 82944 B
#define QH_S 0
#define QR_S (BM * QSTR)

__device__ __align__(16) __half g_qh[BATCH * LSEQ * HD];
__device__ __align__(16) __half g_qr[BATCH * LSEQ * HD];
__device__ __align__(16) __half g_kh[BATCH * LSEQ * HD];
__device__ __align__(16) __half g_kr[BATCH * LSEQ * HD];
__device__ __align__(16) __half g_vh[BATCH * LSEQ * HD];

// ---------------------------------------------------------------------------
__device__ __forceinline__ uint32_t smem_u32(const void* p) {
    uint32_t a;
    asm("{ .reg .u64 t; cvta.to.shared.u64 t, %1; cvt.u32.u64 %0, t; }" : "=r"(a) : "l"(p));
    return a;
}
__device__ __forceinline__ void cp16(uint32_t dst, const void* src) {
    asm volatile("cp.async.ca.shared.global [%0], [%1], 16;" :: "r"(dst), "l"(src));
}
#define CP_COMMIT() asm volatile("cp.async.commit_group;" ::: "memory")
#define CP_WAIT(n)  asm volatile("cp.async.wait_group %0;" :: "n"(n) : "memory")

__device__ __forceinline__ void ldsm4(uint32_t addr, uint32_t& r0, uint32_t& r1,
                                      uint32_t& r2, uint32_t& r3) {
    asm volatile("ldmatrix.sync.aligned.m8n8.x4.shared.b16 {%0,%1,%2,%3}, [%4];"
                 : "=r"(r0), "=r"(r1), "=r"(r2), "=r"(r3) : "r"(addr));
}
__device__ __forceinline__ void ldsm4t(uint32_t addr, uint32_t& r0, uint32_t& r1,
                                       uint32_t& r2, uint32_t& r3) {
    asm volatile("ldmatrix.sync.aligned.m8n8.x4.trans.shared.b16 {%0,%1,%2,%3}, [%4];"
                 : "=r"(r0), "=r"(r1), "=r"(r2), "=r"(r3) : "r"(addr));
}
__device__ __forceinline__ void mma16816(float* c, const uint32_t* a, const uint32_t* b) {
    asm volatile("mma.sync.aligned.m16n8k16.row.col.f32.f16.f16.f32 "
                 "{%0,%1,%2,%3}, {%4,%5,%6,%7}, {%8,%9}, {%0,%1,%2,%3};"
                 : "+f"(c[0]), "+f"(c[1]), "+f"(c[2]), "+f"(c[3])
                 : "r"(a[0]), "r"(a[1]), "r"(a[2]), "r"(a[3]), "r"(b[0]), "r"(b[1]));
}
__device__ __forceinline__ uint32_t packh(__half a, __half b) {
    __half2 h = __halves2half2(a, b);
    return *(uint32_t*)&h;
}
__device__ __forceinline__ uint32_t pack2f(float a, float b) {
    __half2 h = __floats2half2_rn(a, b);
    return *(uint32_t*)&h;
}
__device__ __forceinline__ float ex2f(float x) {
    float y;
    asm("ex2.approx.f32 %0, %1;" : "=f"(y) : "f"(x));
    return y;
}

// ---------------------------------------------------------------------------
// prepass: Q scaled by log2(e), then split hi/resid; K split; V fp16.
// ---------------------------------------------------------------------------
__global__ void prep_kernel(const float4* __restrict__ Q, const float4* __restrict__ K,
                            const float4* __restrict__ V) {
    int i = blockIdx.x * blockDim.x + threadIdx.x;
    float4 q = Q[i], k = K[i], v = V[i];
    const float LG2E = 1.4426950408889634f;
    q.x *= LG2E; q.y *= LG2E; q.z *= LG2E; q.w *= LG2E;

    __half qhx = __float2half_rn(q.x), qhy = __float2half_rn(q.y),
           qhz = __float2half_rn(q.z), qhw = __float2half_rn(q.w);
    __half qrx = __float2half_rn(q.x - __half2float(qhx)),
           qry = __float2half_rn(q.y - __half2float(qhy)),
           qrz = __float2half_rn(q.z - __half2float(qhz)),
           qrw = __float2half_rn(q.w - __half2float(qhw));
    ((uint2*)g_qh)[i] = make_uint2(packh(qhx, qhy), packh(qhz, qhw));
    ((uint2*)g_qr)[i] = make_uint2(packh(qrx, qry), packh(qrz, qrw));

    __half khx = __float2half_rn(k.x), khy = __float2half_rn(k.y),
           khz = __float2half_rn(k.z), khw = __float2half_rn(k.w);
    __half krx = __float2half_rn(k.x - __half2float(khx)),
           kry = __float2half_rn(k.y - __half2float(khy)),
           krz = __float2half_rn(k.z - __half2float(khz)),
           krw = __float2half_rn(k.w - __half2float(khw));
    ((uint2*)g_kh)[i] = make_uint2(packh(khx, khy), packh(khz, khw));
    ((uint2*)g_kr)[i] = make_uint2(packh(krx, kry), packh(krz, krw));

    ((uint2*)g_vh)[i] = make_uint2(pack2f(v.x, v.y), pack2f(v.z, v.w));
}

// ---------------------------------------------------------------------------
__device__ __forceinline__ void issue_tile(uint32_t smb, int stage, int t, int tid,
                                           const __half* kh_g, const __half* kr_g,
                                           const __half* vh_g) {
    const int base = stage * STAGE_HALFS;
    const __half* ks = kh_g + (size_t)t * BN * HD;
    const __half* rs = kr_g + (size_t)t * BN * HD;
    const __half* vs = vh_g + (size_t)t * BN * HD;
#pragma unroll
    for (int i = 0; i < 4; i++) {
        int cid = tid + i * NTHREADS;          // 0..511
        int r = cid >> 3, c = cid & 7;
        uint32_t d = (uint32_t)(r * KSTR * 2 + c * 16);
        const size_t so = (size_t)r * HD + c * 8;
        cp16(smb + (uint32_t)(base + KH_OFF) * 2 + d, ks + so);
        cp16(smb + (uint32_t)(base + KR_OFF) * 2 + d, rs + so);
        cp16(smb + (uint32_t)(base + VH_OFF) * 2 + d, vs + so);
    }
}

// One pipeline step: S(T+1)->SNXT (garbage at T=NTILES-1, discarded),
// softmax(T) on SCUR, PV(T) + ones-column sum MMA.
#define BODY(SCUR, SNXT, T)                                                         \
{                                                                                   \
    CP_WAIT(0);                                                                     \
    __syncthreads();                                                                \
    if ((T) + 2 < NTILES) {                                                         \
        issue_tile(smb, stage2, (T) + 2, tid, kh_g, kr_g, vh_g);                    \
        CP_COMMIT();                                                                \
    }                                                                               \
    /* ---- S(T+1) = Q K^T (3xFP16) into SNXT ---- */                               \
    {                                                                               \
        const uint32_t kb1 = (uint32_t)(stage1 * STAGE_HALFS);                      \
        _Pragma("unroll")                                                           \
        for (int j = 0; j < 8; j++)                                                 \
            _Pragma("unroll")                                                       \
            for (int q = 0; q < 4; q++) SNXT[j][q] = 0.f;                           \
        _Pragma("unroll")                                                           \
        for (int s = 0; s < 4; s++) {                                               \
            uint32_t bb[8][2];                                                      \
            _Pragma("unroll")                                                       \
            for (int jj = 0; jj < 4; jj++) {                                        \
                uint32_t addr = smb + (kb1 + KH_OFF +                               \
                    (uint32_t)((16 * jj + krow_off) * KSTR + 16 * s + kcol_off)) * 2; \
                ldsm4(addr, bb[2*jj][0], bb[2*jj][1], bb[2*jj+1][0], bb[2*jj+1][1]); \
            }                                                                       \
            _Pragma("unroll")                                                       \
            for (int j = 0; j < 8; j++) {                                           \
                mma16816(SNXT[j], qh[s], bb[j]);                                    \
                mma16816(SNXT[j], qr[s], bb[j]);                                    \
            }                                                                       \
            _Pragma("unroll")                                                       \
            for (int jj = 0; jj < 4; jj++) {                                        \
                uint32_t addr = smb + (kb1 + KR_OFF +                               \
                    (uint32_t)((16 * jj + krow_off) * KSTR + 16 * s + kcol_off)) * 2; \
                ldsm4(addr, bb[2*jj][0], bb[2*jj][1], bb[2*jj+1][0], bb[2*jj+1][1]); \
            }                                                                       \
            _Pragma("unroll")                                                       \
            for (int j = 0; j < 8; j++) mma16816(SNXT[j], qh[s], bb[j]);            \
        }                                                                           \
    }                                                                               \
    /* ---- softmax(T) on SCUR (base-2; no sum reduction) ---- */                   \
    uint32_t pa[4][4];                                                              \
    {                                                                               \
        float m0t = SCUR[0][0], m1t = SCUR[0][2];                                   \
        _Pragma("unroll")                                                           \
        for (int j = 0; j < 8; j++) {                                               \
            m0t = fmaxf(m0t, fmaxf(SCUR[j][0], SCUR[j][1]));                        \
            m1t = fmaxf(m1t, fmaxf(SCUR[j][2], SCUR[j][3]));                        \
        }                                                                           \
        m0t = fmaxf(m0t, __shfl_xor_sync(0xffffffffu, m0t, 1));                     \
        m0t = fmaxf(m0t, __shfl_xor_sync(0xffffffffu, m0t, 2));                     \
        m1t = fmaxf(m1t, __shfl_xor_sync(0xffffffffu, m1t, 1));                     \
        m1t = fmaxf(m1t, __shfl_xor_sync(0xffffffffu, m1t, 2));                     \
        const float m0n = fmaxf(m0, m0t), m1n = fmaxf(m1, m1t);                     \
        const float c0 = ex2f(m0 - m0n), c1 = ex2f(m1 - m1n);                       \
        m0 = m0n; m1 = m1n;                                                         \
        _Pragma("unroll")                                                           \
        for (int j = 0; j < 8; j++) {                                               \
            float e0 = ex2f(SCUR[j][0] - m0n);                                      \
            float e1 = ex2f(SCUR[j][1] - m0n);                                      \
            float e2 = ex2f(SCUR[j][2] - m1n);                                      \
            float e3 = ex2f(SCUR[j][3] - m1n);                                      \
            pa[j >> 1][(j & 1) ? 2 : 0] = pack2f(e0, e1);                           \
            pa[j >> 1][(j & 1) ? 3 : 1] = pack2f(e2, e3);                           \
        }                                                                           \
        _Pragma("unroll")                                                           \
        for (int j = 0; j < 8; j++) {                                               \
            o_[j][0] *= c0; o_[j][1] *= c0;                                         \
            o_[j][2] *= c1; o_[j][3] *= c1;                                         \
        }                                                                           \
        osum[0] *= c0; osum[1] *= c0;                                               \
        osum[2] *= c1; osum[3] *= c1;                                               \
    }                                                                               \
    /* ---- O += P V(T); osum += P * ones ---- */                                   \
    {                                                                               \
        const uint32_t kb0 = (uint32_t)(stage0 * STAGE_HALFS);                      \
        _Pragma("unroll")                                                           \
        for (int s = 0; s < 4; s++) {                                               \
            uint32_t vb[8][2];                                                      \
            _Pragma("unroll")                                                       \
            for (int jj = 0; jj < 4; jj++) {                                        \
                uint32_t addr = smb + (kb0 + VH_OFF +                               \
                    (uint32_t)((16 * s + vkey_off) * KSTR + 16 * jj + vcol_off)) * 2; \
                ldsm4t(addr, vb[2*jj][0], vb[2*jj][1], vb[2*jj+1][0], vb[2*jj+1][1]); \
            }                                                                       \
            _Pragma("unroll")                                                       \
            for (int j = 0; j < 8; j++) mma16816(o_[j], pa[s], vb[j]);              \
            mma16816(osum, pa[s], bsum);                                            \
        }                                                                           \
    }                                                                               \
    stage0 = stage1; stage1 = stage2; stage2 = (stage2 == 2) ? 0 : stage2 + 1;      \
}

__global__ __launch_bounds__(NTHREADS, 2)
void attn_mma(float* __restrict__ O) {
    extern __shared__ __half sh[];
    const uint32_t smb = smem_u32(sh);
    const int tid = threadIdx.x, lane = tid & 31, wid = tid >> 5;
    const int g = lane >> 2, tg = lane & 3;
    const int wr0 = wid * 16;
    const int b = blockIdx.y, row0 = blockIdx.x * BM;

    const __half* qh_g = g_qh + (size_t)(b * LSEQ + row0) * HD;
    const __half* qr_g = g_qr + (size_t)(b * LSEQ + row0) * HD;
    const __half* kh_g = g_kh + (size_t)b * LSEQ * HD;
    const __half* kr_g = g_kr + (size_t)b * LSEQ * HD;
    const __half* vh_g = g_vh + (size_t)b * LSEQ * HD;
    float* Ob = O + (size_t)(b * LSEQ + row0) * HD;

    // B fragment for the ones column (n-col 0 of the n8 block = 1, rest 0):
    // lanes 0..3 own n=0 and hold halfs {1,1} in both k-halves.
    uint32_t bsum[2];
    bsum[0] = bsum[1] = (lane < 4) ? 0x3C003C00u : 0u;

    // ---- preamble: Q -> smem -> regs ----
#pragma unroll
    for (int i = 0; i < 4; i++) {
        int cid = tid + i * NTHREADS;          // 0..511
        int r = cid >> 3, c = cid & 7;
        const size_t so = (size_t)r * HD + c * 8;
        cp16(smb + (uint32_t)(QH_S + r * QSTR) * 2 + c * 16, qh_g + so);
        cp16(smb + (uint32_t)(QR_S + r * QSTR) * 2 + c * 16, qr_g + so);
    }
    CP_COMMIT();
    CP_WAIT(0);
    __syncthreads();

    uint32_t qh[4][4], qr[4][4];
    {
        const int arow = wr0 + (lane & 15);
        const int koff = (lane >> 4) << 3;
#pragma unroll
        for (int s = 0; s < 4; s++) {
            uint32_t a1 = smb + (uint32_t)(QH_S + arow * QSTR + 16 * s + koff) * 2;
            uint32_t a2 = smb + (uint32_t)(QR_S + arow * QSTR + 16 * s + koff) * 2;
            ldsm4(a1, qh[s][0], qh[s][1], qh[s][2], qh[s][3]);
            ldsm4(a2, qr[s][0], qr[s][1], qr[s][2], qr[s][3]);
        }
    }
    __syncthreads();   // Q area reusable by pipeline

    issue_tile(smb, 0, 0, tid, kh_g, kr_g, vh_g);
    CP_COMMIT();
    issue_tile(smb, 1, 1, tid, kh_g, kr_g, vh_g);
    CP_COMMIT();

    float o_[8][4], osum[4];
#pragma unroll
    for (int j = 0; j < 8; j++)
#pragma unroll
        for (int q = 0; q < 4; q++) o_[j][q] = 0.f;
#pragma unroll
    for (int q = 0; q < 4; q++) osum[q] = 0.f;
    float m0 = -1e30f, m1 = -1e30f;

    const int krow_off = (lane & 7) + ((lane >> 4) << 3);
    const int kcol_off = (lane & 8);
    const int vkey_off = (lane & 7) + (lane & 8);
    const int vcol_off = (lane >> 4) << 3;

    // ---- prologue: S(0) into sa ----
    float sa[8][4], sb[8][4];
    CP_WAIT(1);            // tile 0 resident
    __syncthreads();
    {
        const uint32_t kb = 0;   // stage 0
#pragma unroll
        for (int j = 0; j < 8; j++)
#pragma unroll
            for (int q = 0; q < 4; q++) sa[j][q] = 0.f;
#pragma unroll
        for (int s = 0; s < 4; s++) {
            uint32_t bb[8][2];
#pragma unroll
            for (int jj = 0; jj < 4; jj++) {
                uint32_t addr = smb + (kb + KH_OFF +
                    (uint32_t)((16 * jj + krow_off) * KSTR + 16 * s + kcol_off)) * 2;
                ldsm4(addr, bb[2*jj][0], bb[2*jj][1], bb[2*jj+1][0], bb[2*jj+1][1]);
            }
#pragma unroll
            for (int j = 0; j < 8; j++) {
                mma16816(sa[j], qh[s], bb[j]);
                mma16816(sa[j], qr[s], bb[j]);
            }
#pragma unroll
            for (int jj = 0; jj < 4; jj++) {
                uint32_t addr = smb + (kb + KR_OFF +
                    (uint32_t)((16 * jj + krow_off) * KSTR + 16 * s + kcol_off)) * 2;
                ldsm4(addr, bb[2*jj][0], bb[2*jj][1], bb[2*jj+1][0], bb[2*jj+1][1]);
            }
#pragma unroll
            for (int j = 0; j < 8; j++) mma16816(sa[j], qh[s], bb[j]);
        }
    }

    int stage0 = 0, stage1 = 1, stage2 = 2;

    for (int t = 0; t < NTILES; t += 2) {
        BODY(sa, sb, t);
        BODY(sb, sa, t + 1);
    }

    // ---- epilogue: l lives in osum (col 64 -> tg==0 lanes); broadcast ----
    const int srcl = lane & ~3;   // tg==0 lane of this quad
    const float l0 = __shfl_sync(0xffffffffu, osum[0], srcl);
    const float l1 = __shfl_sync(0xffffffffu, osum[2], srcl);
    const float inv0 = 1.0f / l0, inv1 = 1.0f / l1;
    const int r0g = wr0 + g, r1g = wr0 + g + 8;
#pragma unroll
    for (int j = 0; j < 8; j++) {
        float2 v0 = make_float2(o_[j][0] * inv0, o_[j][1] * inv0);
        float2 v1 = make_float2(o_[j][2] * inv1, o_[j][3] * inv1);
        *(float2*)&Ob[(size_t)r0g * HD + 8 * j + 2 * tg] = v0;
        *(float2*)&Ob[(size_t)r1g * HD + 8 * j + 2 * tg] = v1;
    }
}

// ---------------------------------------------------------------------------
extern "C" void kernel_launch(void* const* d_in, const int* in_sizes, int n_in,
                              void* d_out, int out_size)
{
    const float* Q = (const float*)d_in[0];
    const float* K = (const float*)d_in[1];
    const float* V = (const float*)d_in[2];
    float*       O = (float*)d_out;

    const int n4 = BATCH * LSEQ * HD / 4;
    prep_kernel<<<n4 / 256, 256>>>((const float4*)Q, (const float4*)K, (const float4*)V);

    cudaFuncSetAttribute(attn_mma, cudaFuncAttributeMaxDynamicSharedMemorySize, SMEM_BYTES);
    dim3 grid(LSEQ / BM, BATCH);
    attn_mma<<<grid, NTHREADS, SMEM_BYTES>>>(O);
}

// round 15
// speedup vs baseline: 1.2705x; 1.0003x over previous
#include <cuda_runtime.h>
#include <cuda_fp16.h>
#include <cstdint>

// ============================================================================
// Flash attention via mma.sync.m16n8k16 (fp16 in, fp32 accum), sm_103 base ISA.
// B=4, L=4096, D=64.  S = Q K^T in 3xFP16 (compensated), online softmax in
// base-2 domain (Q prescaled by log2e), O = P V fp16.
// R11 = R10 + (a) ex2.approx.f16x2 for P (halves MUFU ops),
//             (b) lazy O-rescale skipped when the row max is unchanged.
// ============================================================================

#define LSEQ 4096
#define BATCH 4
#define HD 64
#define BM 64
#define BN 64
#define NTILES (LSEQ / BN)     // 64
#define NTHREADS 128
#define QSTR 72
#define KSTR 72

#define TILE_HALFS (BN * KSTR)            // 4608
#define STAGE_HALFS (3 * TILE_HALFS)      // 13824
#define KH_OFF 0
#define KR_OFF TILE_HALFS
#define VH_OFF (2 * TILE_HALFS)
#define NSTAGES 3
#define SMEM_BYTES (NSTAGES * STAGE_HALFS * 2)   // 82944 B
#define QH_S 0
#define QR_S (BM * QSTR)

__device__ __align__(16) __half g_qh[BATCH * LSEQ * HD];
__device__ __align__(16) __half g_qr[BATCH * LSEQ * HD];
__device__ __align__(16) __half g_kh[BATCH * LSEQ * HD];
__device__ __align__(16) __half g_kr[BATCH * LSEQ * HD];
__device__ __align__(16) __half g_vh[BATCH * LSEQ * HD];

// ---------------------------------------------------------------------------
__device__ __forceinline__ uint32_t smem_u32(const void* p) {
    uint32_t a;
    asm("{ .reg .u64 t; cvta.to.shared.u64 t, %1; cvt.u32.u64 %0, t; }" : "=r"(a) : "l"(p));
    return a;
}
__device__ __forceinline__ void cp16(uint32_t dst, const void* src) {
    asm volatile("cp.async.ca.shared.global [%0], [%1], 16;" :: "r"(dst), "l"(src));
}
#define CP_COMMIT() asm volatile("cp.async.commit_group;" ::: "memory")
#define CP_WAIT(n)  asm volatile("cp.async.wait_group %0;" :: "n"(n) : "memory")

__device__ __forceinline__ void ldsm4(uint32_t addr, uint32_t& r0, uint32_t& r1,
                                      uint32_t& r2, uint32_t& r3) {
    asm volatile("ldmatrix.sync.aligned.m8n8.x4.shared.b16 {%0,%1,%2,%3}, [%4];"
                 : "=r"(r0), "=r"(r1), "=r"(r2), "=r"(r3) : "r"(addr));
}
__device__ __forceinline__ void ldsm4t(uint32_t addr, uint32_t& r0, uint32_t& r1,
                                       uint32_t& r2, uint32_t& r3) {
    asm volatile("ldmatrix.sync.aligned.m8n8.x4.trans.shared.b16 {%0,%1,%2,%3}, [%4];"
                 : "=r"(r0), "=r"(r1), "=r"(r2), "=r"(r3) : "r"(addr));
}
__device__ __forceinline__ void mma16816(float* c, const uint32_t* a, const uint32_t* b) {
    asm volatile("mma.sync.aligned.m16n8k16.row.col.f32.f16.f16.f32 "
                 "{%0,%1,%2,%3}, {%4,%5,%6,%7}, {%8,%9}, {%0,%1,%2,%3};"
                 : "+f"(c[0]), "+f"(c[1]), "+f"(c[2]), "+f"(c[3])
                 : "r"(a[0]), "r"(a[1]), "r"(a[2]), "r"(a[3]), "r"(b[0]), "r"(b[1]));
}
__device__ __forceinline__ uint32_t packh(__half a, __half b) {
    __half2 h = __halves2half2(a, b);
    return *(uint32_t*)&h;
}
__device__ __forceinline__ uint32_t pack2f(float a, float b) {
    __half2 h = __floats2half2_rn(a, b);
    return *(uint32_t*)&h;
}
__device__ __forceinline__ float ex2f(float x) {
    float y;
    asm("ex2.approx.f32 %0, %1;" : "=f"(y) : "f"(x));
    return y;
}
__device__ __forceinline__ uint32_t ex2h2(uint32_t x) {
    uint32_t y;
    asm("ex2.approx.f16x2 %0, %1;" : "=r"(y) : "r"(x));
    return y;
}

// ---------------------------------------------------------------------------
// prepass: Q scaled by log2(e), then split hi/resid; K split; V fp16.
// ---------------------------------------------------------------------------
__global__ void prep_kernel(const float4* __restrict__ Q, const float4* __restrict__ K,
                            const float4* __restrict__ V) {
    int i = blockIdx.x * blockDim.x + threadIdx.x;
    float4 q = Q[i], k = K[i], v = V[i];
    const float LG2E = 1.4426950408889634f;
    q.x *= LG2E; q.y *= LG2E; q.z *= LG2E; q.w *= LG2E;

    __half qhx = __float2half_rn(q.x), qhy = __float2half_rn(q.y),
           qhz = __float2half_rn(q.z), qhw = __float2half_rn(q.w);
    __half qrx = __float2half_rn(q.x - __half2float(qhx)),
           qry = __float2half_rn(q.y - __half2float(qhy)),
           qrz = __float2half_rn(q.z - __half2float(qhz)),
           qrw = __float2half_rn(q.w - __half2float(qhw));
    ((uint2*)g_qh)[i] = make_uint2(packh(qhx, qhy), packh(qhz, qhw));
    ((uint2*)g_qr)[i] = make_uint2(packh(qrx, qry), packh(qrz, qrw));

    __half khx = __float2half_rn(k.x), khy = __float2half_rn(k.y),
           khz = __float2half_rn(k.z), khw = __float2half_rn(k.w);
    __half krx = __float2half_rn(k.x - __half2float(khx)),
           kry = __float2half_rn(k.y - __half2float(khy)),
           krz = __float2half_rn(k.z - __half2float(khz)),
           krw = __float2half_rn(k.w - __half2float(khw));
    ((uint2*)g_kh)[i] = make_uint2(packh(khx, khy), packh(khz, khw));
    ((uint2*)g_kr)[i] = make_uint2(packh(krx, kry), packh(krz, krw));

    ((uint2*)g_vh)[i] = make_uint2(pack2f(v.x, v.y), pack2f(v.z, v.w));
}

// ---------------------------------------------------------------------------
__device__ __forceinline__ void issue_tile(uint32_t smb, int stage, int t, int tid,
                                           const __half* kh_g, const __half* kr_g,
                                           const __half* vh_g) {
    const int base = stage * STAGE_HALFS;
    const __half* ks = kh_g + (size_t)t * BN * HD;
    const __half* rs = kr_g + (size_t)t * BN * HD;
    const __half* vs = vh_g + (size_t)t * BN * HD;
#pragma unroll
    for (int i = 0; i < 4; i++) {
        int cid = tid + i * NTHREADS;          // 0..511
        int r = cid >> 3, c = cid & 7;
        uint32_t d = (uint32_t)(r * KSTR * 2 + c * 16);
        const size_t so = (size_t)r * HD + c * 8;
        cp16(smb + (uint32_t)(base + KH_OFF) * 2 + d, ks + so);
        cp16(smb + (uint32_t)(base + KR_OFF) * 2 + d, rs + so);
        cp16(smb + (uint32_t)(base + VH_OFF) * 2 + d, vs + so);
    }
}

// One pipeline step: S(T+1)->SNXT (garbage at T=NTILES-1, discarded),
// softmax(T) on SCUR, PV(T) + ones-column sum MMA.
#define BODY(SCUR, SNXT, T)                                                         \
{                                                                                   \
    CP_WAIT(0);                                                                     \
    __syncthreads();                                                                \
    if ((T) + 2 < NTILES) {                                                         \
        issue_tile(smb, stage2, (T) + 2, tid, kh_g, kr_g, vh_g);                    \
        CP_COMMIT();                                                                \
    }                                                                               \
    /* ---- S(T+1) = Q K^T (3xFP16) into SNXT ---- */                               \
    {                                                                               \
        const uint32_t kb1 = (uint32_t)(stage1 * STAGE_HALFS);                      \
        _Pragma("unroll")                                                           \
        for (int j = 0; j < 8; j++)                                                 \
            _Pragma("unroll")                                                       \
            for (int q = 0; q < 4; q++) SNXT[j][q] = 0.f;                           \
        _Pragma("unroll")                                                           \
        for (int s = 0; s < 4; s++) {                                               \
            uint32_t bb[8][2];                                                      \
            _Pragma("unroll")                                                       \
            for (int jj = 0; jj < 4; jj++) {                                        \
                uint32_t addr = smb + (kb1 + KH_OFF +                               \
                    (uint32_t)((16 * jj + krow_off) * KSTR + 16 * s + kcol_off)) * 2; \
                ldsm4(addr, bb[2*jj][0], bb[2*jj][1], bb[2*jj+1][0], bb[2*jj+1][1]); \
            }                                                                       \
            _Pragma("unroll")                                                       \
            for (int j = 0; j < 8; j++) {                                           \
                mma16816(SNXT[j], qh[s], bb[j]);                                    \
                mma16816(SNXT[j], qr[s], bb[j]);                                    \
            }                                                                       \
            _Pragma("unroll")                                                       \
            for (int jj = 0; jj < 4; jj++) {                                        \
                uint32_t addr = smb + (kb1 + KR_OFF +                               \
                    (uint32_t)((16 * jj + krow_off) * KSTR + 16 * s + kcol_off)) * 2; \
                ldsm4(addr, bb[2*jj][0], bb[2*jj][1], bb[2*jj+1][0], bb[2*jj+1][1]); \
            }                                                                       \
            _Pragma("unroll")                                                       \
            for (int j = 0; j < 8; j++) mma16816(SNXT[j], qh[s], bb[j]);            \
        }                                                                           \
    }                                                                               \
    /* ---- softmax(T) on SCUR (base-2; fp16x2 exp; lazy rescale) ---- */           \
    uint32_t pa[4][4];                                                              \
    {                                                                               \
        float m0t = SCUR[0][0], m1t = SCUR[0][2];                                   \
        _Pragma("unroll")                                                           \
        for (int j = 0; j < 8; j++) {                                               \
            m0t = fmaxf(m0t, fmaxf(SCUR[j][0], SCUR[j][1]));                        \
            m1t = fmaxf(m1t, fmaxf(SCUR[j][2], SCUR[j][3]));                        \
        }                                                                           \
        m0t = fmaxf(m0t, __shfl_xor_sync(0xffffffffu, m0t, 1));                     \
        m0t = fmaxf(m0t, __shfl_xor_sync(0xffffffffu, m0t, 2));                     \
        m1t = fmaxf(m1t, __shfl_xor_sync(0xffffffffu, m1t, 1));                     \
        m1t = fmaxf(m1t, __shfl_xor_sync(0xffffffffu, m1t, 2));                     \
        const float m0n = fmaxf(m0, m0t), m1n = fmaxf(m1, m1t);                     \
        const bool nochg = (m0n == m0) && (m1n == m1);                              \
        if (!__all_sync(0xffffffffu, nochg)) {                                      \
            const float c0 = ex2f(m0 - m0n), c1 = ex2f(m1 - m1n);                   \
            _Pragma("unroll")                                                       \
            for (int j = 0; j < 8; j++) {                                           \
                o_[j][0] *= c0; o_[j][1] *= c0;                                     \
                o_[j][2] *= c1; o_[j][3] *= c1;                                     \
            }                                                                       \
            osum[0] *= c0; osum[1] *= c0;                                           \
            osum[2] *= c1; osum[3] *= c1;                                           \
        }                                                                           \
        m0 = m0n; m1 = m1n;                                                         \
        _Pragma("unroll")                                                           \
        for (int j = 0; j < 8; j++) {                                               \
            uint32_t x01 = pack2f(SCUR[j][0] - m0n, SCUR[j][1] - m0n);              \
            uint32_t x23 = pack2f(SCUR[j][2] - m1n, SCUR[j][3] - m1n);              \
            pa[j >> 1][(j & 1) ? 2 : 0] = ex2h2(x01);                               \
            pa[j >> 1][(j & 1) ? 3 : 1] = ex2h2(x23);                               \
        }                                                                           \
    }                                                                               \
    /* ---- O += P V(T); osum += P * ones ---- */                                   \
    {                                                                               \
        const uint32_t kb0 = (uint32_t)(stage0 * STAGE_HALFS);                      \
        _Pragma("unroll")                                                           \
        for (int s = 0; s < 4; s++) {                                               \
            uint32_t vb[8][2];                                                      \
            _Pragma("unroll")                                                       \
            for (int jj = 0; jj < 4; jj++) {                                        \
                uint32_t addr = smb + (kb0 + VH_OFF +                               \
                    (uint32_t)((16 * s + vkey_off) * KSTR + 16 * jj + vcol_off)) * 2; \
                ldsm4t(addr, vb[2*jj][0], vb[2*jj][1], vb[2*jj+1][0], vb[2*jj+1][1]); \
            }                                                                       \
            _Pragma("unroll")                                                       \
            for (int j = 0; j < 8; j++) mma16816(o_[j], pa[s], vb[j]);              \
            mma16816(osum, pa[s], bsum);                                            \
        }                                                                           \
    }                                                                               \
    stage0 = stage1; stage1 = stage2; stage2 = (stage2 == 2) ? 0 : stage2 + 1;      \
}

__global__ __launch_bounds__(NTHREADS, 2)
void attn_mma(float* __restrict__ O) {
    extern __shared__ __half sh[];
    const uint32_t smb = smem_u32(sh);
    const int tid = threadIdx.x, lane = tid & 31, wid = tid >> 5;
    const int g = lane >> 2, tg = lane & 3;
    const int wr0 = wid * 16;
    const int b = blockIdx.y, row0 = blockIdx.x * BM;

    const __half* qh_g = g_qh + (size_t)(b * LSEQ + row0) * HD;
    const __half* qr_g = g_qr + (size_t)(b * LSEQ + row0) * HD;
    const __half* kh_g = g_kh + (size_t)b * LSEQ * HD;
    const __half* kr_g = g_kr + (size_t)b * LSEQ * HD;
    const __half* vh_g = g_vh + (size_t)b * LSEQ * HD;
    float* Ob = O + (size_t)(b * LSEQ + row0) * HD;

    // B fragment for the ones column (n-col 0 of the n8 block = 1, rest 0):
    // lanes 0..3 own n=0 and hold halfs {1,1} in both k-halves.
    uint32_t bsum[2];
    bsum[0] = bsum[1] = (lane < 4) ? 0x3C003C00u : 0u;

    // ---- preamble: Q -> smem -> regs ----
#pragma unroll
    for (int i = 0; i < 4; i++) {
        int cid = tid + i * NTHREADS;          // 0..511
        int r = cid >> 3, c = cid & 7;
        const size_t so = (size_t)r * HD + c * 8;
        cp16(smb + (uint32_t)(QH_S + r * QSTR) * 2 + c * 16, qh_g + so);
        cp16(smb + (uint32_t)(QR_S + r * QSTR) * 2 + c * 16, qr_g + so);
    }
    CP_COMMIT();
    CP_WAIT(0);
    __syncthreads();

    uint32_t qh[4][4], qr[4][4];
    {
        const int arow = wr0 + (lane & 15);
        const int koff = (lane >> 4) << 3;
#pragma unroll
        for (int s = 0; s < 4; s++) {
            uint32_t a1 = smb + (uint32_t)(QH_S + arow * QSTR + 16 * s + koff) * 2;
            uint32_t a2 = smb + (uint32_t)(QR_S + arow * QSTR + 16 * s + koff) * 2;
            ldsm4(a1, qh[s][0], qh[s][1], qh[s][2], qh[s][3]);
            ldsm4(a2, qr[s][0], qr[s][1], qr[s][2], qr[s][3]);
        }
    }
    __syncthreads();   // Q area reusable by pipeline

    issue_tile(smb, 0, 0, tid, kh_g, kr_g, vh_g);
    CP_COMMIT();
    issue_tile(smb, 1, 1, tid, kh_g, kr_g, vh_g);
    CP_COMMIT();

    float o_[8][4], osum[4];
#pragma unroll
    for (int j = 0; j < 8; j++)
#pragma unroll
        for (int q = 0; q < 4; q++) o_[j][q] = 0.f;
#pragma unroll
    for (int q = 0; q < 4; q++) osum[q] = 0.f;
    float m0 = -1e30f, m1 = -1e30f;

    const int krow_off = (lane & 7) + ((lane >> 4) << 3);
    const int kcol_off = (lane & 8);
    const int vkey_off = (lane & 7) + (lane & 8);
    const int vcol_off = (lane >> 4) << 3;

    // ---- prologue: S(0) into sa ----
    float sa[8][4], sb[8][4];
    CP_WAIT(1);            // tile 0 resident
    __syncthreads();
    {
        const uint32_t kb = 0;   // stage 0
#pragma unroll
        for (int j = 0; j < 8; j++)
#pragma unroll
            for (int q = 0; q < 4; q++) sa[j][q] = 0.f;
#pragma unroll
        for (int s = 0; s < 4; s++) {
            uint32_t bb[8][2];
#pragma unroll
            for (int jj = 0; jj < 4; jj++) {
                uint32_t addr = smb + (kb + KH_OFF +
                    (uint32_t)((16 * jj + krow_off) * KSTR + 16 * s + kcol_off)) * 2;
                ldsm4(addr, bb[2*jj][0], bb[2*jj][1], bb[2*jj+1][0], bb[2*jj+1][1]);
            }
#pragma unroll
            for (int j = 0; j < 8; j++) {
                mma16816(sa[j], qh[s], bb[j]);
                mma16816(sa[j], qr[s], bb[j]);
            }
#pragma unroll
            for (int jj = 0; jj < 4; jj++) {
                uint32_t addr = smb + (kb + KR_OFF +
                    (uint32_t)((16 * jj + krow_off) * KSTR + 16 * s + kcol_off)) * 2;
                ldsm4(addr, bb[2*jj][0], bb[2*jj][1], bb[2*jj+1][0], bb[2*jj+1][1]);
            }
#pragma unroll
            for (int j = 0; j < 8; j++) mma16816(sa[j], qh[s], bb[j]);
        }
    }

    int stage0 = 0, stage1 = 1, stage2 = 2;

    for (int t = 0; t < NTILES; t += 2) {
        BODY(sa, sb, t);
        BODY(sb, sa, t + 1);
    }

    // ---- epilogue: l lives in osum (col 64 -> tg==0 lanes); broadcast ----
    const int srcl = lane & ~3;   // tg==0 lane of this quad
    const float l0 = __shfl_sync(0xffffffffu, osum[0], srcl);
    const float l1 = __shfl_sync(0xffffffffu, osum[2], srcl);
    const float inv0 = 1.0f / l0, inv1 = 1.0f / l1;
    const int r0g = wr0 + g, r1g = wr0 + g + 8;
#pragma unroll
    for (int j = 0; j < 8; j++) {
        float2 v0 = make_float2(o_[j][0] * inv0, o_[j][1] * inv0);
        float2 v1 = make_float2(o_[j][2] * inv1, o_[j][3] * inv1);
        *(float2*)&Ob[(size_t)r0g * HD + 8 * j + 2 * tg] = v0;
        *(float2*)&Ob[(size_t)r1g * HD + 8 * j + 2 * tg] = v1;
    }
}

// ---------------------------------------------------------------------------
extern "C" void kernel_launch(void* const* d_in, const int* in_sizes, int n_in,
                              void* d_out, int out_size)
{
    const float* Q = (const float*)d_in[0];
    const float* K = (const float*)d_in[1];
    const float* V = (const float*)d_in[2];
    float*       O = (float*)d_out;

    const int n4 = BATCH * LSEQ * HD / 4;
    prep_kernel<<<n4 / 256, 256>>>((const float4*)Q, (const float4*)K, (const float4*)V);

    cudaFuncSetAttribute(attn_mma, cudaFuncAttributeMaxDynamicSharedMemorySize, SMEM_BYTES);
    dim3 grid(LSEQ / BM, BATCH);
    attn_mma<<<grid, NTHREADS, SMEM_BYTES>>>(O);
}